// round 4
// baseline (speedup 1.0000x reference)
#include <cuda_runtime.h>
#include <cuda_bf16.h>
#include <cuda_fp16.h>
#include <cstdint>

#define NN 50000
#define NE 800000

// ---------------- device scratch (no allocs allowed) ----------------
__device__ __align__(16) float g_h[NN * 128];
__device__ __align__(16) __half g_h16[NN * 128];
__device__ __align__(16) __nv_bfloat16 g_xhi[NN * 128];
__device__ __align__(16) __nv_bfloat16 g_xlo[NN * 128];
__device__ __align__(16) __nv_bfloat16 g_whi[5 * 128 * 128];
__device__ __align__(16) __nv_bfloat16 g_wlo[5 * 128 * 128];
__device__ int   g_deg[NN];
__device__ float g_invdeg[NN];
__device__ int   g_rowptr[NN + 1];
__device__ int   g_cursor[NN];
__device__ int   g_esrc[NE];

// ---------------- helpers ----------------
__device__ __forceinline__ uint32_t smem_u32(const void* p) {
    uint32_t a;
    asm("{ .reg .u64 t; cvta.to.shared.u64 t, %1; cvt.u32.u64 %0, t; }" : "=r"(a) : "l"(p));
    return a;
}

__device__ __forceinline__ void ldsm4(uint32_t* r, uint32_t addr) {
    asm volatile("ldmatrix.sync.aligned.m8n8.x4.shared.b16 {%0,%1,%2,%3}, [%4];"
                 : "=r"(r[0]), "=r"(r[1]), "=r"(r[2]), "=r"(r[3]) : "r"(addr));
}

__device__ __forceinline__ void mma_bf16(float* c, const uint32_t* a, const uint32_t* b) {
    asm volatile(
        "mma.sync.aligned.m16n8k16.row.col.f32.bf16.bf16.f32 "
        "{%0,%1,%2,%3}, {%4,%5,%6,%7}, {%8,%9}, {%0,%1,%2,%3};"
        : "+f"(c[0]), "+f"(c[1]), "+f"(c[2]), "+f"(c[3])
        : "r"(a[0]), "r"(a[1]), "r"(a[2]), "r"(a[3]), "r"(b[0]), "r"(b[1]));
}

__device__ __forceinline__ void split_bf16(float v, __nv_bfloat16& hi, __nv_bfloat16& lo) {
    hi = __float2bfloat16_rn(v);
    lo = __float2bfloat16_rn(v - __bfloat162float(hi));
}
__device__ __forceinline__ uint32_t pack2(__nv_bfloat16 a, __nv_bfloat16 b) {
    __nv_bfloat162 t = __halves2bfloat162(a, b);
    return *reinterpret_cast<uint32_t*>(&t);
}
__device__ __forceinline__ uint32_t pack2h(__half a, __half b) {
    __half2 t = __halves2half2(a, b);
    return *reinterpret_cast<uint32_t*>(&t);
}

// ---------------- CSR build ----------------
__global__ void zero_deg_kernel() {
    int v = blockIdx.x * blockDim.x + threadIdx.x;
    if (v < NN) g_deg[v] = 0;
}

__global__ void hist_kernel(const int* __restrict__ dst) {
    int i = blockIdx.x * blockDim.x + threadIdx.x;
    if (i * 4 + 3 < NE) {
        int4 d = ((const int4*)dst)[i];
        atomicAdd(&g_deg[d.x], 1);
        atomicAdd(&g_deg[d.y], 1);
        atomicAdd(&g_deg[d.z], 1);
        atomicAdd(&g_deg[d.w], 1);
    } else {
        for (int e = i * 4; e < NE; ++e) atomicAdd(&g_deg[dst[e]], 1);
    }
}

__global__ void scan_kernel() {
    __shared__ int partial[1024];
    int t = threadIdx.x;
    const int C = (NN + 1023) / 1024;
    int beg = t * C;
    int end = min(beg + C, NN);
    int s = 0;
    for (int v = beg; v < end; ++v) s += g_deg[v];
    partial[t] = s;
    __syncthreads();
    for (int off = 1; off < 1024; off <<= 1) {
        int val = (t >= off) ? partial[t - off] : 0;
        __syncthreads();
        partial[t] += val;
        __syncthreads();
    }
    int run = (t == 0) ? 0 : partial[t - 1];
    for (int v = beg; v < end; ++v) {
        int d = g_deg[v];
        g_rowptr[v] = run;
        g_cursor[v] = 0;
        g_invdeg[v] = 1.0f / (float)(d > 0 ? d : 1);
        run += d;
    }
    if (t == 1023) g_rowptr[NN] = run;
}

__global__ void fill_kernel(const int* __restrict__ src, const int* __restrict__ dst) {
    int i = blockIdx.x * blockDim.x + threadIdx.x;
    if (i * 4 + 3 < NE) {
        int4 s = ((const int4*)src)[i];
        int4 d = ((const int4*)dst)[i];
        int p0 = atomicAdd(&g_cursor[d.x], 1);
        int p1 = atomicAdd(&g_cursor[d.y], 1);
        int p2 = atomicAdd(&g_cursor[d.z], 1);
        int p3 = atomicAdd(&g_cursor[d.w], 1);
        g_esrc[g_rowptr[d.x] + p0] = s.x;
        g_esrc[g_rowptr[d.y] + p1] = s.y;
        g_esrc[g_rowptr[d.z] + p2] = s.z;
        g_esrc[g_rowptr[d.w] + p3] = s.w;
    } else {
        for (int e = i * 4; e < NE; ++e) {
            int d = dst[e];
            int p = atomicAdd(&g_cursor[d], 1);
            g_esrc[g_rowptr[d] + p] = src[e];
        }
    }
}

// ---------------- fp32 -> bf16 split convert ----------------
__global__ void convert_split_kernel(const float* __restrict__ in,
                                     __nv_bfloat16* __restrict__ ohi,
                                     __nv_bfloat16* __restrict__ olo, int n4) {
    int i = blockIdx.x * blockDim.x + threadIdx.x;
    if (i < n4) {
        float4 v = ((const float4*)in)[i];
        __nv_bfloat16 h0, l0, h1, l1, h2, l2, h3, l3;
        split_bf16(v.x, h0, l0);
        split_bf16(v.y, h1, l1);
        split_bf16(v.z, h2, l2);
        split_bf16(v.w, h3, l3);
        uint2 uh, ul;
        uh.x = pack2(h0, h1); uh.y = pack2(h2, h3);
        ul.x = pack2(l0, l1); ul.y = pack2(l2, l3);
        ((uint2*)ohi)[i] = uh;
        ((uint2*)olo)[i] = ul;
    }
}

// ---------------- aggregation (hidden layers): fp16 gather, bf16-split output ----------------
__global__ void aggregate_kernel(const float* __restrict__ h, const __half* __restrict__ h16,
                                 __nv_bfloat16* __restrict__ xhi,
                                 __nv_bfloat16* __restrict__ xlo,
                                 const float* __restrict__ eps, int li) {
    int warp = (blockIdx.x * blockDim.x + threadIdx.x) >> 5;
    if (warp >= NN) return;
    int lane = threadIdx.x & 31;
    int v = warp;
    int beg = g_rowptr[v], end = g_rowptr[v + 1];
    float4 acc = make_float4(0.f, 0.f, 0.f, 0.f);
    int e = beg;
    int col = lane * 4;
#define GATH(uv)                                                        \
    {                                                                   \
        __half2 p0 = *reinterpret_cast<const __half2*>(&(uv).x);        \
        __half2 p1 = *reinterpret_cast<const __half2*>(&(uv).y);        \
        float2 f0 = __half22float2(p0);                                 \
        float2 f1 = __half22float2(p1);                                 \
        acc.x += f0.x; acc.y += f0.y; acc.z += f1.x; acc.w += f1.y;     \
    }
    for (; e + 4 <= end; e += 4) {
        int s0 = g_esrc[e + 0];
        int s1 = g_esrc[e + 1];
        int s2 = g_esrc[e + 2];
        int s3 = g_esrc[e + 3];
        uint2 a = *(const uint2*)(h16 + (size_t)s0 * 128 + col);
        uint2 b = *(const uint2*)(h16 + (size_t)s1 * 128 + col);
        uint2 c = *(const uint2*)(h16 + (size_t)s2 * 128 + col);
        uint2 d = *(const uint2*)(h16 + (size_t)s3 * 128 + col);
        GATH(a); GATH(b); GATH(c); GATH(d);
    }
    for (; e < end; ++e) {
        int s = g_esrc[e];
        uint2 a = *(const uint2*)(h16 + (size_t)s * 128 + col);
        GATH(a);
    }
#undef GATH
    float inv = g_invdeg[v];
    float sc = 1.0f + eps[li];
    float4 hv = *(const float4*)(h + (size_t)v * 128 + col);
    float4 o;
    o.x = sc * hv.x + acc.x * inv;
    o.y = sc * hv.y + acc.y * inv;
    o.z = sc * hv.z + acc.z * inv;
    o.w = sc * hv.w + acc.w * inv;
    __nv_bfloat16 h0, l0, h1, l1, h2, l2, h3, l3;
    split_bf16(o.x, h0, l0);
    split_bf16(o.y, h1, l1);
    split_bf16(o.z, h2, l2);
    split_bf16(o.w, h3, l3);
    uint2 uh, ul;
    uh.x = pack2(h0, h1); uh.y = pack2(h2, h3);
    ul.x = pack2(l0, l1); ul.y = pack2(l2, l3);
    *(uint2*)&xhi[(size_t)v * 128 + col] = uh;
    *(uint2*)&xlo[(size_t)v * 128 + col] = ul;
}

// ---------------- final aggregation (64 feats, post-GEMM reorder) ----------------
__global__ void aggregate_last_kernel(const float* __restrict__ z, const __half* __restrict__ z16,
                                      float* __restrict__ out,
                                      const float* __restrict__ eps,
                                      const float* __restrict__ bl) {
    int warp = (blockIdx.x * blockDim.x + threadIdx.x) >> 5;
    if (warp >= NN) return;
    int lane = threadIdx.x & 31;
    int v = warp;
    int beg = g_rowptr[v], end = g_rowptr[v + 1];
    float2 acc = make_float2(0.f, 0.f);
    int e = beg;
    int col = lane * 2;
#define GATH2(u)                                                       \
    {                                                                  \
        __half2 p = *reinterpret_cast<const __half2*>(&(u));           \
        float2 f = __half22float2(p);                                  \
        acc.x += f.x; acc.y += f.y;                                    \
    }
    for (; e + 4 <= end; e += 4) {
        int s0 = g_esrc[e + 0];
        int s1 = g_esrc[e + 1];
        int s2 = g_esrc[e + 2];
        int s3 = g_esrc[e + 3];
        uint32_t a = *(const uint32_t*)(z16 + (size_t)s0 * 64 + col);
        uint32_t b = *(const uint32_t*)(z16 + (size_t)s1 * 64 + col);
        uint32_t c = *(const uint32_t*)(z16 + (size_t)s2 * 64 + col);
        uint32_t d = *(const uint32_t*)(z16 + (size_t)s3 * 64 + col);
        GATH2(a); GATH2(b); GATH2(c); GATH2(d);
    }
    for (; e < end; ++e) {
        int s = g_esrc[e];
        uint32_t a = *(const uint32_t*)(z16 + (size_t)s * 64 + col);
        GATH2(a);
    }
#undef GATH2
    float inv = g_invdeg[v];
    float sc = 1.0f + eps[3];
    float2 zv = *(const float2*)(z + (size_t)v * 64 + col);
    float2 o;
    o.x = sc * zv.x + acc.x * inv + bl[col];
    o.y = sc * zv.y + acc.y * inv + bl[col + 1];
    *(float2*)(out + (size_t)v * 64 + col) = o;
}

// ---------------- h fp32 -> bf16 split (for last-layer GEMM input) ----------------
__global__ void split_h_kernel(const float* __restrict__ h,
                               __nv_bfloat16* __restrict__ xhi,
                               __nv_bfloat16* __restrict__ xlo) {
    int i = blockIdx.x * blockDim.x + threadIdx.x;
    if (i < NN * 128 / 4) {
        float4 v = ((const float4*)h)[i];
        __nv_bfloat16 h0, l0, h1, l1, h2, l2, h3, l3;
        split_bf16(v.x, h0, l0);
        split_bf16(v.y, h1, l1);
        split_bf16(v.z, h2, l2);
        split_bf16(v.w, h3, l3);
        uint2 uh, ul;
        uh.x = pack2(h0, h1); uh.y = pack2(h2, h3);
        ul.x = pack2(l0, l1); ul.y = pack2(l2, l3);
        ((uint2*)xhi)[i] = uh;
        ((uint2*)xlo)[i] = ul;
    }
}

// ---------------- tensor-core GEMM via mma.sync (bf16 split, fp32 accum) ----------------
template <int N, bool RELU, bool BIAS>
__global__ void __launch_bounds__(256) gemm_mma(
    const __nv_bfloat16* __restrict__ Ahi, const __nv_bfloat16* __restrict__ Alo,
    const __nv_bfloat16* __restrict__ Bhi, const __nv_bfloat16* __restrict__ Blo,
    const float* __restrict__ bias, float* __restrict__ out, __half* __restrict__ out16,
    int M) {
    constexpr int LD = 136;
    constexpr int NWN = N / 32;
    constexpr int NWM = 8 / NWN;
    constexpr int MW = 128 / NWM;
    constexpr int MT = MW / 16;

    extern __shared__ __nv_bfloat16 sm[];
    __nv_bfloat16* sAhi = sm;
    __nv_bfloat16* sAlo = sAhi + 128 * LD;
    __nv_bfloat16* sBhi = sAlo + 128 * LD;
    __nv_bfloat16* sBlo = sBhi + N * LD;
    __shared__ float s_bias[128];

    int tid = threadIdx.x;
    int m0 = blockIdx.x * 128;
    if (BIAS) {
        if (tid < N) s_bias[tid] = bias[tid];
    }

    for (int i = tid; i < 2048; i += 256) {
        int row = i >> 4;
        int c8 = (i & 15) << 3;
        int gm = m0 + row;
        uint4 vh = make_uint4(0, 0, 0, 0), vl = make_uint4(0, 0, 0, 0);
        if (gm < M) {
            vh = *(const uint4*)(Ahi + (size_t)gm * 128 + c8);
            vl = *(const uint4*)(Alo + (size_t)gm * 128 + c8);
        }
        *(uint4*)&sAhi[row * LD + c8] = vh;
        *(uint4*)&sAlo[row * LD + c8] = vl;
    }
    for (int i = tid; i < N * 16; i += 256) {
        int row = i >> 4;
        int c8 = (i & 15) << 3;
        *(uint4*)&sBhi[row * LD + c8] = *(const uint4*)(Bhi + (size_t)row * 128 + c8);
        *(uint4*)&sBlo[row * LD + c8] = *(const uint4*)(Blo + (size_t)row * 128 + c8);
    }
    __syncthreads();

    int lane = tid & 31;
    int wid = tid >> 5;
    int wm = wid / NWN;
    int wn = wid % NWN;

    float acc[MT][4][4];
#pragma unroll
    for (int mt = 0; mt < MT; ++mt)
#pragma unroll
        for (int nt = 0; nt < 4; ++nt)
#pragma unroll
            for (int q = 0; q < 4; ++q) acc[mt][nt][q] = 0.f;

    const int ar = lane & 15;
    const int ak = (lane >> 4) << 3;
    const int br = (lane & 7) + ((lane >> 4) << 3);
    const int bk = ((lane >> 3) & 1) << 3;

#pragma unroll
    for (int ks = 0; ks < 8; ++ks) {
        int k0 = ks << 4;
        uint32_t ah[MT][4], al[MT][4];
#pragma unroll
        for (int mt = 0; mt < MT; ++mt) {
            int row = wm * MW + mt * 16 + ar;
            ldsm4(ah[mt], smem_u32(&sAhi[row * LD + k0 + ak]));
            ldsm4(al[mt], smem_u32(&sAlo[row * LD + k0 + ak]));
        }
        uint32_t bh[4][2], bl[4][2];
#pragma unroll
        for (int p = 0; p < 2; ++p) {
            int nrow = wn * 32 + p * 16 + br;
            uint32_t r[4];
            ldsm4(r, smem_u32(&sBhi[nrow * LD + k0 + bk]));
            bh[2 * p][0] = r[0]; bh[2 * p][1] = r[1];
            bh[2 * p + 1][0] = r[2]; bh[2 * p + 1][1] = r[3];
            ldsm4(r, smem_u32(&sBlo[nrow * LD + k0 + bk]));
            bl[2 * p][0] = r[0]; bl[2 * p][1] = r[1];
            bl[2 * p + 1][0] = r[2]; bl[2 * p + 1][1] = r[3];
        }
#pragma unroll
        for (int mt = 0; mt < MT; ++mt)
#pragma unroll
            for (int nt = 0; nt < 4; ++nt) {
                mma_bf16(acc[mt][nt], ah[mt], bh[nt]);
                mma_bf16(acc[mt][nt], ah[mt], bl[nt]);
                mma_bf16(acc[mt][nt], al[mt], bh[nt]);
            }
    }

    int r = lane >> 2;
    int c2 = (lane & 3) << 1;
#pragma unroll
    for (int mt = 0; mt < MT; ++mt) {
        int gm = m0 + wm * MW + mt * 16 + r;
#pragma unroll
        for (int nt = 0; nt < 4; ++nt) {
            int col = wn * 32 + nt * 8 + c2;
            float b0 = BIAS ? s_bias[col] : 0.f;
            float b1 = BIAS ? s_bias[col + 1] : 0.f;
            if (gm < M) {
                float2 v = make_float2(acc[mt][nt][0] + b0, acc[mt][nt][1] + b1);
                if (RELU) { v.x = fmaxf(v.x, 0.f); v.y = fmaxf(v.y, 0.f); }
                *(float2*)(out + (size_t)gm * N + col) = v;
                *(uint32_t*)(out16 + (size_t)gm * N + col) =
                    pack2h(__float2half_rn(v.x), __float2half_rn(v.y));
            }
            if (gm + 8 < M) {
                float2 v = make_float2(acc[mt][nt][2] + b0, acc[mt][nt][3] + b1);
                if (RELU) { v.x = fmaxf(v.x, 0.f); v.y = fmaxf(v.y, 0.f); }
                *(float2*)(out + (size_t)(gm + 8) * N + col) = v;
                *(uint32_t*)(out16 + (size_t)(gm + 8) * N + col) =
                    pack2h(__float2half_rn(v.x), __float2half_rn(v.y));
            }
        }
    }
}

// ---------------- launch ----------------
extern "C" void kernel_launch(void* const* d_in, const int* in_sizes, int n_in,
                              void* d_out, int out_size) {
    const float* inputs = (const float*)d_in[0];
    const float* fc_W   = (const float*)d_in[1];
    const float* fc_b   = (const float*)d_in[2];
    const float* W      = (const float*)d_in[3];
    const float* b      = (const float*)d_in[4];
    const float* W_last = (const float*)d_in[5];
    const float* b_last = (const float*)d_in[6];
    const float* eps    = (const float*)d_in[7];
    const int*   src    = (const int*)d_in[8];
    const int*   dst    = (const int*)d_in[9];
    float* out = (float*)d_out;

    float* hptr;
    __half* h16;
    __nv_bfloat16 *xhi, *xlo, *whi, *wlo;
    cudaGetSymbolAddress((void**)&hptr, g_h);
    cudaGetSymbolAddress((void**)&h16, g_h16);
    cudaGetSymbolAddress((void**)&xhi, g_xhi);
    cudaGetSymbolAddress((void**)&xlo, g_xlo);
    cudaGetSymbolAddress((void**)&whi, g_whi);
    cudaGetSymbolAddress((void**)&wlo, g_wlo);

    const int SMEM128 = (2 * 128 * 136 + 2 * 128 * 136) * 2;  // 139264 B
    const int SMEM64  = (2 * 128 * 136 + 2 * 64 * 136) * 2;   // 104448 B
    cudaFuncSetAttribute(gemm_mma<128, true, true>, cudaFuncAttributeMaxDynamicSharedMemorySize, SMEM128);
    cudaFuncSetAttribute(gemm_mma<64, false, false>, cudaFuncAttributeMaxDynamicSharedMemorySize, SMEM64);

    // CSR build
    zero_deg_kernel<<<(NN + 255) / 256, 256>>>();
    hist_kernel<<<(NE / 4 + 255) / 256, 256>>>(dst);
    scan_kernel<<<1, 1024>>>();
    fill_kernel<<<(NE / 4 + 255) / 256, 256>>>(src, dst);

    // weight + input bf16 splits
    convert_split_kernel<<<(16384 / 4 + 255) / 256, 256>>>(fc_W, whi, wlo, 16384 / 4);
    convert_split_kernel<<<(49152 / 4 + 255) / 256, 256>>>(W, whi + 16384, wlo + 16384, 49152 / 4);
    convert_split_kernel<<<(8192 / 4 + 255) / 256, 256>>>(W_last, whi + 4 * 16384, wlo + 4 * 16384, 8192 / 4);
    convert_split_kernel<<<(NN * 128 / 4 + 255) / 256, 256>>>(inputs, xhi, xlo, NN * 128 / 4);

    const int gemm_grid = (NN + 127) / 128;  // 391
    const int agg_grid  = (NN + 7) / 8;

    // input SLP (writes h fp32 + fp16)
    gemm_mma<128, true, true><<<gemm_grid, 256, SMEM128>>>(xhi, xlo, whi, wlo, fc_b, hptr, h16, NN);

    // 3 hidden GIN layers
    for (int i = 0; i < 3; ++i) {
        aggregate_kernel<<<agg_grid, 256>>>(hptr, h16, xhi, xlo, eps, i);
        gemm_mma<128, true, true><<<gemm_grid, 256, SMEM128>>>(
            xhi, xlo, whi + (size_t)(1 + i) * 16384, wlo + (size_t)(1 + i) * 16384,
            b + (size_t)i * 128, hptr, h16, NN);
    }

    // last layer reordered: z = h@WL (no bias/relu), then out = (1+eps3)z + agg(z16) + bL
    split_h_kernel<<<(NN * 128 / 4 + 255) / 256, 256>>>(hptr, xhi, xlo);
    gemm_mma<64, false, false><<<gemm_grid, 256, SMEM64>>>(
        xhi, xlo, whi + (size_t)4 * 16384, wlo + (size_t)4 * 16384, nullptr, hptr, h16, NN);
    aggregate_last_kernel<<<agg_grid, 256>>>(hptr, h16, out, eps, b_last);

    (void)in_sizes; (void)n_in; (void)out_size;
}